// round 4
// baseline (speedup 1.0000x reference)
#include <cuda_runtime.h>

// Problem constants
#define BB  2048   // batch
#define TT  2      // timesteps
#define NZ  100    // zones
#define SS  6      // state
#define HH  64     // hidden (actor + critic)
#define G3  192    // 3*H gate rows
#define NBF 35     // neighbor feature size
#define LMH 128    // localized module hidden

// Actor output scratch, layout Aflat[n*(B*T) + b*T + t]  (== flatten of [N,B,T])
// so that the reference's transpose(2,0,1).reshape(B,T,N) becomes:
//   p[b,t,n] = Aflat[200*b + 100*t + n]
__device__ float g_Aflat[NZ * BB * TT];

__device__ __forceinline__ float fsig(float x) {
    return __fdividef(1.0f, 1.0f + __expf(-x));
}
__device__ __forceinline__ float ftanh(float x) {
    return 1.0f - __fdividef(2.0f, __expf(2.0f * x) + 1.0f);
}

// ---------------------------------------------------------------------------
// Actor: one CTA per (zone n, 256-batch tile). Thread = one batch row.
// ---------------------------------------------------------------------------
__global__ __launch_bounds__(256, 1)
void actor_kernel(const float* __restrict__ x,
                  const float* __restrict__ Wih, const float* __restrict__ Whh,
                  const float* __restrict__ bih, const float* __restrict__ bhh,
                  const float* __restrict__ W1,  const float* __restrict__ b1,
                  const float* __restrict__ W2,  const float* __restrict__ b2,
                  const float* __restrict__ W3,  const float* __restrict__ b3)
{
    extern __shared__ float sm[];
    float* sWhh = sm;                   // 12288
    float* sW1  = sWhh + G3 * HH;       // 4096
    float* sW2  = sW1 + HH * HH;        // 4096
    float* sWih = sW2 + HH * HH;        // 1152
    float* sbih = sWih + G3 * SS;       // 192
    float* sbhh = sbih + G3;            // 192
    float* sb1  = sbhh + G3;            // 64
    float* sb2  = sb1 + HH;             // 64
    float* sW3  = sb2 + HH;             // 64
    float* sb3  = sW3 + HH;             // 4 (1 used)
    float* scr1 = sb3 + 4;              // 64*256
    float* scr2 = scr1 + HH * 256;      // 64*256

    const int n   = blockIdx.y;
    const int tid = threadIdx.x;
    const int b   = (blockIdx.x << 8) + tid;

    for (int i = tid; i < G3 * HH; i += 256) sWhh[i] = Whh[n * G3 * HH + i];
    for (int i = tid; i < HH * HH; i += 256) sW1[i]  = W1[n * HH * HH + i];
    for (int i = tid; i < HH * HH; i += 256) sW2[i]  = W2[n * HH * HH + i];
    for (int i = tid; i < G3 * SS; i += 256) sWih[i] = Wih[n * G3 * SS + i];
    if (tid < G3) { sbih[tid] = bih[n * G3 + tid]; sbhh[tid] = bhh[n * G3 + tid]; }
    if (tid < HH) { sb1[tid] = b1[n * HH + tid]; sb2[tid] = b2[n * HH + tid]; sW3[tid] = W3[n * HH + tid]; }
    if (tid == 0) sb3[0] = b3[n];
    __syncthreads();

    float h[HH];
#pragma unroll
    for (int k = 0; k < HH; k++) h[k] = 0.0f;

#pragma unroll
    for (int t = 0; t < TT; t++) {
        float xs[SS];
#pragma unroll
        for (int s = 0; s < SS; s++) xs[s] = x[((b * TT + t) * NZ + n) * SS + s];

        // --- GRU gates (PyTorch order r,z,n) ---
#pragma unroll 2
        for (int g = 0; g < HH; g++) {
            float ar = sbih[g]        + sbhh[g];
            float az = sbih[HH + g]   + sbhh[HH + g];
            float an = sbih[2*HH + g];
            float ah = sbhh[2*HH + g];
            const float* wr = sWih + g * SS;
            const float* wz = sWih + (HH + g) * SS;
            const float* wn = sWih + (2*HH + g) * SS;
#pragma unroll
            for (int s = 0; s < SS; s++) {
                ar = fmaf(wr[s], xs[s], ar);
                az = fmaf(wz[s], xs[s], az);
                an = fmaf(wn[s], xs[s], an);
            }
            const float4* vr = (const float4*)(sWhh + g * HH);
            const float4* vz = (const float4*)(sWhh + (HH + g) * HH);
            const float4* vn = (const float4*)(sWhh + (2*HH + g) * HH);
#pragma unroll
            for (int k = 0; k < HH / 4; k++) {
                float4 a = vr[k], bq = vz[k], c = vn[k];
                ar = fmaf(a.x,  h[4*k+0], ar); ar = fmaf(a.y,  h[4*k+1], ar);
                ar = fmaf(a.z,  h[4*k+2], ar); ar = fmaf(a.w,  h[4*k+3], ar);
                az = fmaf(bq.x, h[4*k+0], az); az = fmaf(bq.y, h[4*k+1], az);
                az = fmaf(bq.z, h[4*k+2], az); az = fmaf(bq.w, h[4*k+3], az);
                ah = fmaf(c.x,  h[4*k+0], ah); ah = fmaf(c.y,  h[4*k+1], ah);
                ah = fmaf(c.z,  h[4*k+2], ah); ah = fmaf(c.w,  h[4*k+3], ah);
            }
            float r  = fsig(ar);
            float z  = fsig(az);
            float nn = ftanh(fmaf(r, ah, an));
            scr1[g * 256 + tid] = (1.0f - z) * nn;   // (1-z)*n
            scr2[g * 256 + tid] = z;                 // z
        }
        // h_new[k] = (1-z)*n + z*h_old[k]  (same-thread SMEM, no barrier needed)
#pragma unroll
        for (int k = 0; k < HH; k++) h[k] = scr1[k * 256 + tid] + scr2[k * 256 + tid] * h[k];

        // --- MLP head: relu(h) -> 64 -> 64 -> 1 -> 3*(sigmoid-0.5) ---
        float v[HH];
#pragma unroll
        for (int k = 0; k < HH; k++) v[k] = fmaxf(h[k], 0.0f);

#pragma unroll 2
        for (int g = 0; g < HH; g++) {
            float acc = sb1[g];
            const float4* w = (const float4*)(sW1 + g * HH);
#pragma unroll
            for (int k = 0; k < HH / 4; k++) {
                float4 a = w[k];
                acc = fmaf(a.x, v[4*k+0], acc); acc = fmaf(a.y, v[4*k+1], acc);
                acc = fmaf(a.z, v[4*k+2], acc); acc = fmaf(a.w, v[4*k+3], acc);
            }
            scr1[g * 256 + tid] = fmaxf(acc, 0.0f);
        }
#pragma unroll
        for (int k = 0; k < HH; k++) v[k] = scr1[k * 256 + tid];

#pragma unroll 2
        for (int g = 0; g < HH; g++) {
            float acc = sb2[g];
            const float4* w = (const float4*)(sW2 + g * HH);
#pragma unroll
            for (int k = 0; k < HH / 4; k++) {
                float4 a = w[k];
                acc = fmaf(a.x, v[4*k+0], acc); acc = fmaf(a.y, v[4*k+1], acc);
                acc = fmaf(a.z, v[4*k+2], acc); acc = fmaf(a.w, v[4*k+3], acc);
            }
            scr1[g * 256 + tid] = fmaxf(acc, 0.0f);
        }
#pragma unroll
        for (int k = 0; k < HH; k++) v[k] = scr1[k * 256 + tid];

        float acc = sb3[0];
#pragma unroll
        for (int k = 0; k < HH; k++) acc = fmaf(sW3[k], v[k], acc);
        float act = 3.0f * (fsig(acc) - 0.5f);

        g_Aflat[n * (BB * TT) + b * TT + t] = act;
    }
}

// ---------------------------------------------------------------------------
// p output: out_p[b*100+n] = p[b, T-1, n] = Aflat[200b + 100 + n]
// ---------------------------------------------------------------------------
__global__ void pcopy_kernel(float* __restrict__ out)
{
    int idx = blockIdx.x * 256 + threadIdx.x;
    if (idx < BB * NZ) {
        int b = idx / NZ, n = idx % NZ;
        out[idx] = g_Aflat[200 * b + 100 + n];
    }
}

// ---------------------------------------------------------------------------
// Critic + LocalizedModule: warp-per-batch-row.
// ---------------------------------------------------------------------------
__global__ __launch_bounds__(256, 1)
void critic_kernel(const float* __restrict__ x,
                   const float* __restrict__ lmW1, const float* __restrict__ lmb1,
                   const float* __restrict__ lmW2, const float* __restrict__ lmb2,
                   const float* __restrict__ lmW3, const float* __restrict__ lmb3,
                   const float* __restrict__ scWih, const float* __restrict__ scWhh,
                   const float* __restrict__ scbih, const float* __restrict__ scbhh,
                   const float* __restrict__ scW1,  const float* __restrict__ scb1,
                   const float* __restrict__ scW2,  const float* __restrict__ scb2,
                   const float* __restrict__ scW3,  const float* __restrict__ scb3,
                   float* __restrict__ out)
{
    extern __shared__ float sm[];
    float* sWih = sm;                    // [i][g]  35*192
    float* sWhh = sWih + NBF * G3;       // [k][g]  64*192
    float* sW1  = sWhh + HH * G3;        // [k][j]  64*64
    float* sW2  = sW1 + HH * HH;         // [k][j]  64*64
    float* sW3  = sW2 + HH * HH;         // 64
    float* sbih = sW3 + HH;              // 192
    float* sbhh = sbih + G3;             // 192
    float* sb1  = sbhh + G3;             // 64
    float* sb2  = sb1 + HH;              // 64
    float* sb3c = sb2 + HH;              // 4 (1 used)
    float* sLW1 = sb3c + 4;              // [i][j]  35*128
    float* sLW2 = sLW1 + NBF * LMH;      // [k][j]  128*128
    float* sLW3 = sLW2 + LMH * LMH;      // 128
    float* sLb1 = sLW3 + LMH;            // 128
    float* sLb2 = sLb1 + LMH;            // 128
    float* sLb3 = sLb2 + LMH;            // 4 (1 used)
    float* sXi  = sLb3 + 4;              // 8 warps * 2*35
    float* sH   = sXi + 8 * 2 * NBF;     // 8 warps * 64
    float* sBuf = sH + 8 * HH;           // 8 warps * 128

    const int tid = threadIdx.x;

    // Coalesced global reads, transposed SMEM writes.
    for (int idx = tid; idx < G3 * NBF; idx += 256) { int g = idx / NBF, i = idx % NBF; sWih[i * G3 + g] = scWih[idx]; }
    for (int idx = tid; idx < G3 * HH;  idx += 256) { int g = idx / HH,  k = idx % HH;  sWhh[k * G3 + g] = scWhh[idx]; }
    for (int idx = tid; idx < HH * HH;  idx += 256) { int j = idx / HH,  k = idx % HH;  sW1[k * HH + j]  = scW1[idx]; }
    for (int idx = tid; idx < HH * HH;  idx += 256) { int j = idx / HH,  k = idx % HH;  sW2[k * HH + j]  = scW2[idx]; }
    for (int idx = tid; idx < LMH * NBF; idx += 256) { int j = idx / NBF, i = idx % NBF; sLW1[i * LMH + j] = lmW1[idx]; }
    for (int idx = tid; idx < LMH * LMH; idx += 256) { int j = idx / LMH, k = idx % LMH; sLW2[k * LMH + j] = lmW2[idx]; }
    if (tid < G3)  { sbih[tid] = scbih[tid]; sbhh[tid] = scbhh[tid]; }
    if (tid < HH)  { sW3[tid] = scW3[tid]; sb1[tid] = scb1[tid]; sb2[tid] = scb2[tid]; }
    if (tid < LMH) { sLW3[tid] = lmW3[tid]; sLb1[tid] = lmb1[tid]; sLb2[tid] = lmb2[tid]; }
    if (tid == 0)  { sb3c[0] = scb3[0]; sLb3[0] = lmb3[0]; }
    __syncthreads();

    const int w = tid >> 5, l = tid & 31;
    const int b = (blockIdx.x << 3) + w;
    float* xi = sXi + w * (2 * NBF);
    float* hs = sH + w * HH;
    float* bf = sBuf + w * LMH;

    // Build xi[t][35]: [xc99(7), xc89(7), zeros(7), zeros(7), xc98(7)]
    // NBF=35 > warpSize, so each lane covers i = l and i = l+32.
    for (int i = l; i < NBF; i += 32) {
#pragma unroll
        for (int t = 0; t < TT; t++) {
            float v;
            if (i < 6)        v = x[((b * TT + t) * NZ + 99) * SS + i];
            else if (i == 6)  v = g_Aflat[200 * b + 100 * t + 99];
            else if (i < 13)  v = x[((b * TT + t) * NZ + 89) * SS + (i - 7)];
            else if (i == 13) v = g_Aflat[200 * b + 100 * t + 89];
            else if (i < 28)  v = 0.0f;
            else if (i < 34)  v = x[((b * TT + t) * NZ + 98) * SS + (i - 28)];
            else              v = g_Aflat[200 * b + 100 * t + 98];
            xi[t * NBF + i] = v;
        }
    }
    hs[l] = 0.0f; hs[l + 32] = 0.0f;
    __syncwarp();

    const int u0 = l, u1 = l + 32;

    // --- SubCritic GRU, 2 steps. Lane owns hidden units u0, u1. ---
    for (int t = 0; t < TT; t++) {
        float ar0 = sbih[u0] + sbhh[u0], az0 = sbih[64 + u0] + sbhh[64 + u0];
        float an0 = sbih[128 + u0],      ah0 = sbhh[128 + u0];
        float ar1 = sbih[u1] + sbhh[u1], az1 = sbih[64 + u1] + sbhh[64 + u1];
        float an1 = sbih[128 + u1],      ah1 = sbhh[128 + u1];
        const float* xit = xi + t * NBF;
#pragma unroll
        for (int i = 0; i < NBF; i++) {
            float xv = xit[i];
            const float* wc = sWih + i * G3;
            ar0 = fmaf(wc[u0],      xv, ar0); az0 = fmaf(wc[64 + u0],  xv, az0); an0 = fmaf(wc[128 + u0], xv, an0);
            ar1 = fmaf(wc[u1],      xv, ar1); az1 = fmaf(wc[64 + u1],  xv, az1); an1 = fmaf(wc[128 + u1], xv, an1);
        }
        // Recurrent terms: r/z parts go to ar/az; the n-gate recurrent term goes
        // to ah (so that n = tanh(xn + r*(Whh_n h + bhh_n)) matches the GRU).
#pragma unroll
        for (int k = 0; k < HH; k++) {
            float hk = hs[k];
            const float* wc = sWhh + k * G3;
            ar0 = fmaf(wc[u0],      hk, ar0); az0 = fmaf(wc[64 + u0],  hk, az0); ah0 = fmaf(wc[128 + u0], hk, ah0);
            ar1 = fmaf(wc[u1],      hk, ar1); az1 = fmaf(wc[64 + u1],  hk, az1); ah1 = fmaf(wc[128 + u1], hk, ah1);
        }
        float r0 = fsig(ar0), z0 = fsig(az0), n0 = ftanh(fmaf(r0, ah0, an0));
        float r1 = fsig(ar1), z1 = fsig(az1), n1 = ftanh(fmaf(r1, ah1, an1));
        float hn0 = (1.0f - z0) * n0 + z0 * hs[u0];
        float hn1 = (1.0f - z1) * n1 + z1 * hs[u1];
        __syncwarp();
        hs[u0] = hn0; hs[u1] = hn1;
        __syncwarp();
    }

    // --- q MLP: relu(h) -> 64 -> 64 -> 1 ---
    float a0 = sb1[u0], a1 = sb1[u1];
#pragma unroll
    for (int k = 0; k < HH; k++) {
        float ck = fmaxf(hs[k], 0.0f);
        a0 = fmaf(sW1[k * HH + u0], ck, a0);
        a1 = fmaf(sW1[k * HH + u1], ck, a1);
    }
    bf[u0] = fmaxf(a0, 0.0f); bf[u1] = fmaxf(a1, 0.0f);
    __syncwarp();
    a0 = sb2[u0]; a1 = sb2[u1];
#pragma unroll
    for (int k = 0; k < HH; k++) {
        float ck = bf[k];
        a0 = fmaf(sW2[k * HH + u0], ck, a0);
        a1 = fmaf(sW2[k * HH + u1], ck, a1);
    }
    float part = sW3[u0] * fmaxf(a0, 0.0f) + sW3[u1] * fmaxf(a1, 0.0f);
#pragma unroll
    for (int off = 16; off > 0; off >>= 1) part += __shfl_xor_sync(0xffffffffu, part, off);
    float q = part + sb3c[0];
    __syncwarp();   // all bf reads done before LM reuses bf

    // --- LocalizedModule on xi[t=1]: 35 -> 128 -> 128 -> 1. Lane owns 4 units. ---
    const int v0 = l, v1 = l + 32, v2 = l + 64, v3 = l + 96;
    float f0 = sLb1[v0], f1 = sLb1[v1], f2 = sLb1[v2], f3 = sLb1[v3];
    const float* xit = xi + NBF;
#pragma unroll
    for (int i = 0; i < NBF; i++) {
        float xv = xit[i];
        const float* wc = sLW1 + i * LMH;
        f0 = fmaf(wc[v0], xv, f0); f1 = fmaf(wc[v1], xv, f1);
        f2 = fmaf(wc[v2], xv, f2); f3 = fmaf(wc[v3], xv, f3);
    }
    bf[v0] = fmaxf(f0, 0.0f); bf[v1] = fmaxf(f1, 0.0f);
    bf[v2] = fmaxf(f2, 0.0f); bf[v3] = fmaxf(f3, 0.0f);
    __syncwarp();
    f0 = sLb2[v0]; f1 = sLb2[v1]; f2 = sLb2[v2]; f3 = sLb2[v3];
#pragma unroll 8
    for (int k = 0; k < LMH; k++) {
        float ck = bf[k];
        const float* wc = sLW2 + k * LMH;
        f0 = fmaf(wc[v0], ck, f0); f1 = fmaf(wc[v1], ck, f1);
        f2 = fmaf(wc[v2], ck, f2); f3 = fmaf(wc[v3], ck, f3);
    }
    float pf = sLW3[v0] * fmaxf(f0, 0.0f) + sLW3[v1] * fmaxf(f1, 0.0f)
             + sLW3[v2] * fmaxf(f2, 0.0f) + sLW3[v3] * fmaxf(f3, 0.0f);
#pragma unroll
    for (int off = 16; off > 0; off >>= 1) pf += __shfl_xor_sync(0xffffffffu, pf, off);

    if (l == 0) out[BB * NZ + b] = (pf + sLb3[0]) + q;
}

// ---------------------------------------------------------------------------
extern "C" void kernel_launch(void* const* d_in, const int* in_sizes, int n_in,
                              void* d_out, int out_size)
{
    const float* x      = (const float*)d_in[0];
    const float* a_Wih  = (const float*)d_in[1];
    const float* a_Whh  = (const float*)d_in[2];
    const float* a_bih  = (const float*)d_in[3];
    const float* a_bhh  = (const float*)d_in[4];
    const float* a_W1   = (const float*)d_in[5];
    const float* a_b1   = (const float*)d_in[6];
    const float* a_W2   = (const float*)d_in[7];
    const float* a_b2   = (const float*)d_in[8];
    const float* a_W3   = (const float*)d_in[9];
    const float* a_b3   = (const float*)d_in[10];
    const float* lm_W1  = (const float*)d_in[11];
    const float* lm_b1  = (const float*)d_in[12];
    const float* lm_W2  = (const float*)d_in[13];
    const float* lm_b2  = (const float*)d_in[14];
    const float* lm_W3  = (const float*)d_in[15];
    const float* lm_b3  = (const float*)d_in[16];
    const float* sc_Wih = (const float*)d_in[17];
    const float* sc_Whh = (const float*)d_in[18];
    const float* sc_bih = (const float*)d_in[19];
    const float* sc_bhh = (const float*)d_in[20];
    const float* sc_W1  = (const float*)d_in[21];
    const float* sc_b1  = (const float*)d_in[22];
    const float* sc_W2  = (const float*)d_in[23];
    const float* sc_b2  = (const float*)d_in[24];
    const float* sc_W3  = (const float*)d_in[25];
    const float* sc_b3  = (const float*)d_in[26];
    float* out = (float*)d_out;

    // Actor SMEM: weights (22212 floats incl. pad) + 2 * 64*256 scratch
    constexpr size_t SMA = (size_t)(12288 + 4096 + 4096 + 1152 + 192 + 192 + 64 + 64 + 64 + 4
                                    + 2 * 64 * 256) * sizeof(float);
    // Critic SMEM
    constexpr size_t SMC = (size_t)(35*192 + 64*192 + 64*64 + 64*64 + 64 + 192 + 192 + 64 + 64 + 4
                                    + 35*128 + 128*128 + 128 + 128 + 128 + 4
                                    + 8 * (2*35) + 8 * 64 + 8 * 128) * sizeof(float);

    cudaFuncSetAttribute(actor_kernel,  cudaFuncAttributeMaxDynamicSharedMemorySize, (int)SMA);
    cudaFuncSetAttribute(critic_kernel, cudaFuncAttributeMaxDynamicSharedMemorySize, (int)SMC);

    actor_kernel<<<dim3(BB / 256, NZ), 256, SMA>>>(
        x, a_Wih, a_Whh, a_bih, a_bhh, a_W1, a_b1, a_W2, a_b2, a_W3, a_b3);

    pcopy_kernel<<<(BB * NZ + 255) / 256, 256>>>(out);

    critic_kernel<<<BB / 8, 256, SMC>>>(
        x, lm_W1, lm_b1, lm_W2, lm_b2, lm_W3, lm_b3,
        sc_Wih, sc_Whh, sc_bih, sc_bhh, sc_W1, sc_b1, sc_W2, sc_b2, sc_W3, sc_b3,
        out);
}